// round 12
// baseline (speedup 1.0000x reference)
#include <cuda_runtime.h>
#include <cuda_bf16.h>
#include <math.h>
#include <float.h>
#include <stdint.h>

#define NROWS 8192
#define FDIM 256
#define NCLS 64
#define KNNK 5
#define MAXSTEPS 100
#define NCAND 16
#define LOOPBLK 256

// ---------------- device scratch ----------------
__device__ float          g_fn[NROWS * FDIM];
__device__ __nv_bfloat16  g_fnb[NROWS * FDIM];
__device__ float          g_sq[NROWS];
__device__ __nv_bfloat16  g_dotsb[(size_t)NROWS * NROWS];   // 128 MB approx dots
__device__ float          g_unary[NROWS * NCLS];
__device__ float          g_Ya[NROWS * NCLS];
__device__ float          g_Yb[NROWS * NCLS];
__device__ int            g_idx[NROWS * KNNK];
__device__ __align__(16) int g_chg[2][LOOPBLK];   // parity-buffered per-block changed flags
__device__ __align__(16) int g_arrive[LOOPBLK];   // per-block epoch flags (monotonic)

// ---------------- helpers ----------------
__device__ __forceinline__ uint32_t smem_u32(const void* p) {
    uint32_t a;
    asm("{ .reg .u64 t; cvta.to.shared.u64 t, %1; cvt.u32.u64 %0, t; }" : "=r"(a) : "l"(p));
    return a;
}
__device__ __forceinline__ uint32_t packbf(float lo, float hi) {
    uint32_t r;
    asm("cvt.rn.bf16x2.f32 %0, %1, %2;" : "=r"(r) : "f"(hi), "f"(lo)); // d.lo = %2
    return r;
}
__device__ __forceinline__ void cp_async16(uint32_t saddr, const void* gaddr) {
    asm volatile("cp.async.cg.shared.global [%0], [%1], 16;" :: "r"(saddr), "l"(gaddr));
}
__device__ __forceinline__ void cp_commit() { asm volatile("cp.async.commit_group;"); }
__device__ __forceinline__ void cp_wait0() { asm volatile("cp.async.wait_group 0;"); }

// ---------------- init ----------------
__global__ void init_kernel() {
    if (threadIdx.x < LOOPBLK) g_arrive[threadIdx.x] = 0;
}

// ---------------- normalize feats (fp32 + bf16), compute sq ----------------
__global__ void normalize_kernel(const float* __restrict__ feats) {
    int row = blockIdx.x;
    int t = threadIdx.x;
    __shared__ float red[8];
    float x = feats[row * FDIM + t];
    float v = x * x;
    #pragma unroll
    for (int o = 16; o; o >>= 1) v += __shfl_xor_sync(0xffffffffu, v, o);
    if ((t & 31) == 0) red[t >> 5] = v;
    __syncthreads();
    float tot = red[0] + red[1] + red[2] + red[3] + red[4] + red[5] + red[6] + red[7];
    float y = x / fmaxf(sqrtf(tot), 1e-12f);
    g_fn[row * FDIM + t] = y;
    g_fnb[row * FDIM + t] = __float2bfloat16(y);
    float v2 = y * y;
    #pragma unroll
    for (int o = 16; o; o >>= 1) v2 += __shfl_xor_sync(0xffffffffu, v2, o);
    __syncthreads();
    if ((t & 31) == 0) red[t >> 5] = v2;
    __syncthreads();
    if (t == 0)
        g_sq[row] = red[0] + red[1] + red[2] + red[3] + red[4] + red[5] + red[6] + red[7];
}

// ---------------- unary + Y0 ----------------
__global__ void unary_y0_kernel(const float* __restrict__ scores) {
    int w = blockIdx.x * (blockDim.x >> 5) + (threadIdx.x >> 5);
    int lane = threadIdx.x & 31;
    if (w >= NROWS) return;
    float2 s = *(const float2*)(scores + w * NCLS + lane * 2);
    float u0 = -logf(s.x + 1e-10f);
    float u1 = -logf(s.y + 1e-10f);
    *(float2*)(g_unary + w * NCLS + lane * 2) = make_float2(u0, u1);
    float z0 = -u0, z1 = -u1;
    float m = fmaxf(z0, z1);
    #pragma unroll
    for (int o = 16; o; o >>= 1) m = fmaxf(m, __shfl_xor_sync(0xffffffffu, m, o));
    float e0 = expf(z0 - m), e1 = expf(z1 - m);
    float sm = e0 + e1;
    #pragma unroll
    for (int o = 16; o; o >>= 1) sm += __shfl_xor_sync(0xffffffffu, sm, o);
    float inv = 1.f / sm;
    *(float2*)(g_Ya + w * NCLS + lane * 2) = make_float2(e0 * inv, e1 * inv);
}

// ---------------- bf16 mma.sync symmetric GEMM: g_dotsb = fnb @ fnb^T ----------------
#define BM 128
#define BN 128
#define BKC 32
#define AST 40     // padded smem row stride (bf16): 80 B
#define TST 136    // transpose-staging stride (bf16): 272 B (16B aligned)
#define NBLK (NROWS / BM) // 64

__global__ void __launch_bounds__(256) gemm_mma_kernel() {
    __shared__ __align__(16) unsigned char pool[40960];
    __nv_bfloat16 (*As)[BM][AST] = (__nv_bfloat16 (*)[BM][AST])pool;
    __nv_bfloat16 (*Bs)[BN][AST] = (__nv_bfloat16 (*)[BN][AST])(pool + 20480);
    __nv_bfloat16 (*Ts)[TST] = (__nv_bfloat16 (*)[TST])pool;  // reused for mirror

    // triangular block decode
    int tt = blockIdx.x, bi = 0;
    while (tt >= NBLK - bi) { tt -= NBLK - bi; bi++; }
    int bj = bi + tt;
    int iBase = bi * BM, jBase = bj * BN;

    int tid = threadIdx.x, lane = tid & 31, wid = tid >> 5;
    int wm = wid & 1, wn = wid >> 1;   // warp tile 64x32 at (wm*64, wn*32)

    int lrow = tid >> 2;
    int lch = (tid & 3) * 8;
    const __nv_bfloat16* gA = g_fnb + (size_t)(iBase + lrow) * FDIM + lch;
    const __nv_bfloat16* gB = g_fnb + (size_t)(jBase + lrow) * FDIM + lch;

    float acc[4][4][4];
    #pragma unroll
    for (int mi = 0; mi < 4; ++mi)
        #pragma unroll
        for (int ni = 0; ni < 4; ++ni)
            #pragma unroll
            for (int q = 0; q < 4; ++q) acc[mi][ni][q] = 0.f;

    int aRow = wm * 64 + (lane & 15);
    int aCol = ((lane >> 4) << 3);
    int bRow = wn * 32 + (lane & 7);
    int bCol = ((lane >> 3) & 1) << 3;

    cp_async16(smem_u32(&As[0][lrow][lch]), gA);
    cp_async16(smem_u32(&As[0][lrow + 64][lch]), gA + 64 * FDIM);
    cp_async16(smem_u32(&Bs[0][lrow][lch]), gB);
    cp_async16(smem_u32(&Bs[0][lrow + 64][lch]), gB + 64 * FDIM);
    cp_commit();

    #pragma unroll 1
    for (int kk = 0; kk < FDIM / BKC; ++kk) {
        int buf = kk & 1;
        cp_wait0();
        __syncthreads();
        if (kk < FDIM / BKC - 1) {
            int nb = buf ^ 1, k0 = (kk + 1) * BKC;
            cp_async16(smem_u32(&As[nb][lrow][lch]), gA + k0);
            cp_async16(smem_u32(&As[nb][lrow + 64][lch]), gA + 64 * FDIM + k0);
            cp_async16(smem_u32(&Bs[nb][lrow][lch]), gB + k0);
            cp_async16(smem_u32(&Bs[nb][lrow + 64][lch]), gB + 64 * FDIM + k0);
            cp_commit();
        }
        #pragma unroll
        for (int ks = 0; ks < 2; ++ks) {
            int k0 = ks * 16;
            uint32_t a[4][4], b[4][2];
            #pragma unroll
            for (int mi = 0; mi < 4; ++mi) {
                uint32_t ad = smem_u32(&As[buf][aRow + mi * 16][k0 + aCol]);
                asm volatile(
                    "ldmatrix.sync.aligned.m8n8.x4.shared.b16 {%0,%1,%2,%3}, [%4];"
                    : "=r"(a[mi][0]), "=r"(a[mi][1]), "=r"(a[mi][2]), "=r"(a[mi][3])
                    : "r"(ad));
            }
            #pragma unroll
            for (int ni = 0; ni < 4; ++ni) {
                uint32_t bd = smem_u32(&Bs[buf][bRow + ni * 8][k0 + bCol]);
                asm volatile(
                    "ldmatrix.sync.aligned.m8n8.x2.shared.b16 {%0,%1}, [%2];"
                    : "=r"(b[ni][0]), "=r"(b[ni][1])
                    : "r"(bd));
            }
            #pragma unroll
            for (int mi = 0; mi < 4; ++mi)
                #pragma unroll
                for (int ni = 0; ni < 4; ++ni)
                    asm volatile(
                        "mma.sync.aligned.m16n8k16.row.col.f32.bf16.bf16.f32 "
                        "{%0,%1,%2,%3}, {%4,%5,%6,%7}, {%8,%9}, {%0,%1,%2,%3};"
                        : "+f"(acc[mi][ni][0]), "+f"(acc[mi][ni][1]),
                          "+f"(acc[mi][ni][2]), "+f"(acc[mi][ni][3])
                        : "r"(a[mi][0]), "r"(a[mi][1]), "r"(a[mi][2]), "r"(a[mi][3]),
                          "r"(b[ni][0]), "r"(b[ni][1]));
        }
        __syncthreads();
    }

    // main tile write (rows iBase block, cols jBase block)
    int r0 = wm * 64 + (lane >> 2);
    int c0 = wn * 32 + (lane & 3) * 2;
    #pragma unroll
    for (int mi = 0; mi < 4; ++mi)
        #pragma unroll
        for (int ni = 0; ni < 4; ++ni) {
            size_t row = (size_t)(iBase + r0 + mi * 16);
            int col = jBase + c0 + ni * 8;
            *(uint32_t*)(g_dotsb + row * NROWS + col) =
                packbf(acc[mi][ni][0], acc[mi][ni][1]);
            *(uint32_t*)(g_dotsb + (row + 8) * NROWS + col) =
                packbf(acc[mi][ni][2], acc[mi][ni][3]);
        }

    // mirror: stage transposed bf16 tile in smem, write coalesced
    if (bi != bj) {
        #pragma unroll
        for (int mi = 0; mi < 4; ++mi)
            #pragma unroll
            for (int ni = 0; ni < 4; ++ni) {
                int rr = r0 + mi * 16;
                int cc = c0 + ni * 8;
                Ts[cc][rr]         = __float2bfloat16(acc[mi][ni][0]);
                Ts[cc + 1][rr]     = __float2bfloat16(acc[mi][ni][1]);
                Ts[cc][rr + 8]     = __float2bfloat16(acc[mi][ni][2]);
                Ts[cc + 1][rr + 8] = __float2bfloat16(acc[mi][ni][3]);
            }
        __syncthreads();
        #pragma unroll
        for (int q = 0; q < 8; ++q) {
            int idx = q * 256 + tid;       // 2048 uint4 chunks: 16 chunks per 128-col row
            int c = idx >> 4;              // 0..127
            int ch = (idx & 15) * 8;       // 0..120
            uint4 v = *(const uint4*)&Ts[c][ch];
            *(uint4*)(g_dotsb + (size_t)(jBase + c) * NROWS + iBase + ch) = v;
        }
    }
}

// ---------------- fused top-16 + exact refine -> top-5 neighbors ----------------
__device__ __forceinline__ bool cless(float v1, int i1, float v2, int i2) {
    return (v1 < v2) || (v1 == v2 && i1 < i2);
}

__global__ void __launch_bounds__(128) knn_kernel() {
    int row = blockIdx.x;
    int t = threadIdx.x, lane = t & 31, wid = t >> 5;
    float sqi = g_sq[row];
    const __nv_bfloat16* __restrict__ dr = g_dotsb + (size_t)row * NROWS;
    const float* __restrict__ sq = g_sq;

    float bv[NCAND]; int bx[NCAND];
    #pragma unroll
    for (int k = 0; k < NCAND; ++k) { bv[k] = FLT_MAX; bx[k] = 0x7fffffff; }

    for (int s = 0; s < 8; ++s) {
        int j0 = (s * 128 + t) * 8;
        uint4 v = *(const uint4*)(dr + j0);
        uint32_t u[4] = {v.x, v.y, v.z, v.w};
        float4 q0 = *(const float4*)(sq + j0);
        float4 q1 = *(const float4*)(sq + j0 + 4);
        float qq[8] = {q0.x, q0.y, q0.z, q0.w, q1.x, q1.y, q1.z, q1.w};
        #pragma unroll
        for (int p = 0; p < 4; ++p) {
            __nv_bfloat162 bb = *(__nv_bfloat162*)&u[p];
            #pragma unroll
            for (int h = 0; h < 2; ++h) {
                int jj = j0 + p * 2 + h;
                float dot = h ? __bfloat162float(bb.y) : __bfloat162float(bb.x);
                float d = fmaxf(sqi + qq[p * 2 + h] - 2.f * dot, 0.f);
                if (cless(d, jj, bv[NCAND - 1], bx[NCAND - 1])) {
                    bv[NCAND - 1] = d; bx[NCAND - 1] = jj;
                    #pragma unroll
                    for (int k = NCAND - 1; k > 0; --k) {
                        bool sw = cless(bv[k], bx[k], bv[k - 1], bx[k - 1]);
                        float tv = bv[k - 1]; int ti = bx[k - 1];
                        bv[k - 1] = sw ? bv[k] : bv[k - 1];
                        bx[k - 1] = sw ? bx[k] : bx[k - 1];
                        bv[k] = sw ? tv : bv[k];
                        bx[k] = sw ? ti : bx[k];
                    }
                }
            }
        }
    }

    __shared__ float sv[2][128 * NCAND];
    __shared__ int   si[2][128 * NCAND];
    #pragma unroll
    for (int k = 0; k < NCAND; ++k) { sv[0][t * NCAND + k] = bv[k]; si[0][t * NCAND + k] = bx[k]; }

    int cur = 0;
    for (int s = 64; s >= 1; s >>= 1) {
        __syncthreads();
        if (t < s) {
            const float* Av = &sv[cur][t * NCAND];       const int* Ai = &si[cur][t * NCAND];
            const float* Bv = &sv[cur][(t + s) * NCAND]; const int* Bi = &si[cur][(t + s) * NCAND];
            float* Ov = &sv[cur ^ 1][t * NCAND];         int* Oi = &si[cur ^ 1][t * NCAND];
            int p = 0, q = 0;
            #pragma unroll
            for (int r = 0; r < NCAND; ++r) {
                float av = Av[p]; int ai = Ai[p];
                float bw = Bv[q]; int bi2 = Bi[q];
                if (cless(av, ai, bw, bi2)) { Ov[r] = av; Oi[r] = ai; ++p; }
                else                        { Ov[r] = bw; Oi[r] = bi2; ++q; }
            }
        }
        cur ^= 1;
    }
    __syncthreads();

    // refine: exact fp32 dists for the 16 candidates (4 per warp)
    __shared__ int   sc[NCAND];
    __shared__ float sdv[NCAND];
    __shared__ int   sdj[NCAND];
    if (t < NCAND) sc[t] = si[cur][t];
    __syncthreads();

    const float* fr = g_fn + (size_t)row * FDIM;
    float4 m0 = *(const float4*)(fr + lane * 8);
    float4 m1 = *(const float4*)(fr + lane * 8 + 4);
    #pragma unroll
    for (int c = 0; c < 4; ++c) {
        int ci = wid * 4 + c;
        int j = sc[ci];
        const float* fj = g_fn + (size_t)j * FDIM;
        float4 a0 = *(const float4*)(fj + lane * 8);
        float4 a1 = *(const float4*)(fj + lane * 8 + 4);
        float acc = m0.x * a0.x + m0.y * a0.y + m0.z * a0.z + m0.w * a0.w
                  + m1.x * a1.x + m1.y * a1.y + m1.z * a1.z + m1.w * a1.w;
        #pragma unroll
        for (int o = 16; o; o >>= 1) acc += __shfl_xor_sync(0xffffffffu, acc, o);
        if (lane == 0) {
            sdv[ci] = fmaxf(sqi + g_sq[j] - 2.f * acc, 0.f);
            sdj[ci] = j;
        }
    }
    __syncthreads();
    if (t == 0) {
        #pragma unroll
        for (int r = 0; r < KNNK; ++r) {
            float best = FLT_MAX; int bi2 = 0x7fffffff, bc = -1;
            for (int c = 0; c < NCAND; ++c)
                if (sdj[c] != row && cless(sdv[c], sdj[c], best, bi2)) {
                    best = sdv[c]; bi2 = sdj[c]; bc = c;
                }
            g_idx[row * KNNK + r] = bi2;
            sdv[bc] = FLT_MAX; sdj[bc] = 0x7fffffff;
        }
    }
}

// ---------------- persistent fused mean-field loop ----------------
// R10 shape (256 blocks x 256 threads, warp-per-row float2), no energy:
// exit on bitwise Y fixed point (output bit-identical to 100 iterations).
#define RPB (NROWS / LOOPBLK)   // 32 rows per block

__global__ void __launch_bounds__(256) loop_kernel(float* __restrict__ out) {
    __shared__ unsigned sChg[8];
    __shared__ int sCv;
    int b = blockIdx.x, tid = threadIdx.x, wip = tid >> 5, lane = tid & 31;
    int row0 = b * RPB;

    // iteration-invariant registers: unary, own Y, neighbor offsets
    float u0[4], u1[4], y0[4], y1[4];
    int off[4][KNNK];
    #pragma unroll
    for (int q = 0; q < 4; ++q) {
        int row = row0 + wip * 4 + q;
        float2 uu = *(const float2*)(g_unary + (size_t)row * NCLS + lane * 2);
        u0[q] = uu.x; u1[q] = uu.y;
        float2 yy = *(const float2*)(g_Ya + (size_t)row * NCLS + lane * 2);
        y0[q] = yy.x; y1[q] = yy.y;
        #pragma unroll
        for (int j = 0; j < KNNK; ++j)
            off[q][j] = g_idx[row * KNNK + j] * NCLS + lane * 2;
    }

    int finalIt = MAXSTEPS - 1;

    for (int it = 0; it < MAXSTEPS; ++it) {
        const float* Yold = (it & 1) ? g_Yb : g_Ya;
        float* Ynew = (it & 1) ? g_Ya : g_Yb;
        unsigned chg = 0;
        #pragma unroll
        for (int q = 0; q < 4; ++q) {
            int row = row0 + wip * 4 + q;
            float2 p0 = __ldcg((const float2*)(Yold + off[q][0]));
            float2 p1 = __ldcg((const float2*)(Yold + off[q][1]));
            float2 p2 = __ldcg((const float2*)(Yold + off[q][2]));
            float2 p3 = __ldcg((const float2*)(Yold + off[q][3]));
            float2 p4 = __ldcg((const float2*)(Yold + off[q][4]));
            float z0 = -u0[q] + p0.x + p1.x + p2.x + p3.x + p4.x;
            float z1 = -u1[q] + p0.y + p1.y + p2.y + p3.y + p4.y;
            float m = fmaxf(z0, z1);
            #pragma unroll
            for (int o = 16; o; o >>= 1) m = fmaxf(m, __shfl_xor_sync(0xffffffffu, m, o));
            float e0 = __expf(z0 - m), e1 = __expf(z1 - m);
            float sm = e0 + e1;
            #pragma unroll
            for (int o = 16; o; o >>= 1) sm += __shfl_xor_sync(0xffffffffu, sm, o);
            float inv = 1.f / sm;
            float n0 = e0 * inv, n1 = e1 * inv;
            chg |= (__float_as_uint(n0) ^ __float_as_uint(y0[q]))
                 | (__float_as_uint(n1) ^ __float_as_uint(y1[q]));
            y0[q] = n0; y1[q] = n1;
            __stcg((float2*)(Ynew + (size_t)row * NCLS + lane * 2), make_float2(n0, n1));
        }
        unsigned bal = __ballot_sync(0xffffffffu, chg != 0);
        if (lane == 0) sChg[wip] = bal;
        __syncthreads();
        // tid0 publishes (cumulativity: syncthreads + single fence orders all stores)
        if (tid == 0) {
            unsigned c = sChg[0] | sChg[1] | sChg[2] | sChg[3]
                       | sChg[4] | sChg[5] | sChg[6] | sChg[7];
            __stcg(&g_chg[it & 1][b], (int)(c != 0));
            __threadfence();
            __stcg(&g_arrive[b], it + 1);
        }
        if (wip == 0) {
            const int4* fp = (const int4*)&g_arrive[lane * 8];
            for (;;) {
                int4 fa = __ldcg(fp);
                int4 fb = __ldcg(fp + 1);
                int mn = min(min(min(fa.x, fa.y), min(fa.z, fa.w)),
                             min(min(fb.x, fb.y), min(fb.z, fb.w)));
                #pragma unroll
                for (int o = 16; o; o >>= 1)
                    mn = min(mn, __shfl_xor_sync(0xffffffffu, mn, o));
                if (mn >= it + 1) break;
                __nanosleep(20);
            }
            __threadfence();
            // stable parity slot (overwritten only after everyone passed barrier it+2)
            const int4* cp = (const int4*)&g_chg[it & 1][lane * 8];
            int4 ca = __ldcg(cp);
            int4 cb = __ldcg(cp + 1);
            int any = (ca.x | ca.y) | (ca.z | ca.w) | (cb.x | cb.y) | (cb.z | cb.w);
            #pragma unroll
            for (int o = 16; o; o >>= 1) any |= __shfl_xor_sync(0xffffffffu, any, o);
            if (lane == 0) sCv = (any == 0);
        }
        __syncthreads();
        if (sCv) { finalIt = it; break; }   // bitwise fixed point: rest are no-ops
    }
    (void)finalIt;

    // final output from registers
    #pragma unroll
    for (int q = 0; q < 4; ++q) {
        int row = row0 + wip * 4 + q;
        *(float2*)(out + (size_t)row * NCLS + lane * 2) = make_float2(y0[q], y1[q]);
    }
}

// ---------------- host entry ----------------
extern "C" void kernel_launch(void* const* d_in, const int* in_sizes, int n_in,
                              void* d_out, int out_size) {
    const float* scores = (const float*)d_in[0];
    const float* feats  = (const float*)d_in[1];
    if (n_in >= 2 && in_sizes[0] == NROWS * FDIM) {
        scores = (const float*)d_in[1];
        feats  = (const float*)d_in[0];
    }
    (void)out_size;

    init_kernel<<<1, 256>>>();
    normalize_kernel<<<NROWS, FDIM>>>(feats);
    unary_y0_kernel<<<NROWS / 8, 256>>>(scores);
    gemm_mma_kernel<<<NBLK * (NBLK + 1) / 2, 256>>>();
    knn_kernel<<<NROWS, 128>>>();
    loop_kernel<<<LOOPBLK, 256>>>((float*)d_out);
}

// round 13
// speedup vs baseline: 2.0174x; 2.0174x over previous
#include <cuda_runtime.h>
#include <cuda_bf16.h>
#include <math.h>
#include <float.h>
#include <stdint.h>

#define NROWS 8192
#define FDIM 256
#define NCLS 64
#define KNNK 5
#define MAXSTEPS 100
#define NCAND 16

// ---------------- device scratch ----------------
__device__ float          g_fn[NROWS * FDIM];
__device__ __nv_bfloat16  g_fnb[NROWS * FDIM];
__device__ float          g_sq[NROWS];
__device__ __nv_bfloat16  g_dotsb[(size_t)NROWS * NROWS];   // 128 MB approx dots
__device__ float          g_unary[NROWS * NCLS];
__device__ float          g_Ya[NROWS * NCLS];
__device__ float          g_Yb[NROWS * NCLS];
__device__ int            g_idx[NROWS * KNNK];

// ---------------- helpers ----------------
__device__ __forceinline__ uint32_t smem_u32(const void* p) {
    uint32_t a;
    asm("{ .reg .u64 t; cvta.to.shared.u64 t, %1; cvt.u32.u64 %0, t; }" : "=r"(a) : "l"(p));
    return a;
}
__device__ __forceinline__ uint32_t packbf(float lo, float hi) {
    uint32_t r;
    asm("cvt.rn.bf16x2.f32 %0, %1, %2;" : "=r"(r) : "f"(hi), "f"(lo)); // d.lo = %2
    return r;
}
__device__ __forceinline__ void cp_async16(uint32_t saddr, const void* gaddr) {
    asm volatile("cp.async.cg.shared.global [%0], [%1], 16;" :: "r"(saddr), "l"(gaddr));
}
__device__ __forceinline__ void cp_commit() { asm volatile("cp.async.commit_group;"); }
__device__ __forceinline__ void cp_wait0() { asm volatile("cp.async.wait_group 0;"); }

// ---------------- normalize feats (fp32 + bf16), compute sq ----------------
__global__ void normalize_kernel(const float* __restrict__ feats) {
    int row = blockIdx.x;
    int t = threadIdx.x;
    __shared__ float red[8];
    float x = feats[row * FDIM + t];
    float v = x * x;
    #pragma unroll
    for (int o = 16; o; o >>= 1) v += __shfl_xor_sync(0xffffffffu, v, o);
    if ((t & 31) == 0) red[t >> 5] = v;
    __syncthreads();
    float tot = red[0] + red[1] + red[2] + red[3] + red[4] + red[5] + red[6] + red[7];
    float y = x / fmaxf(sqrtf(tot), 1e-12f);
    g_fn[row * FDIM + t] = y;
    g_fnb[row * FDIM + t] = __float2bfloat16(y);
    float v2 = y * y;
    #pragma unroll
    for (int o = 16; o; o >>= 1) v2 += __shfl_xor_sync(0xffffffffu, v2, o);
    __syncthreads();
    if ((t & 31) == 0) red[t >> 5] = v2;
    __syncthreads();
    if (t == 0)
        g_sq[row] = red[0] + red[1] + red[2] + red[3] + red[4] + red[5] + red[6] + red[7];
}

// ---------------- unary + Y0 ----------------
__global__ void unary_y0_kernel(const float* __restrict__ scores) {
    int w = blockIdx.x * (blockDim.x >> 5) + (threadIdx.x >> 5);
    int lane = threadIdx.x & 31;
    if (w >= NROWS) return;
    float2 s = *(const float2*)(scores + w * NCLS + lane * 2);
    float u0 = -logf(s.x + 1e-10f);
    float u1 = -logf(s.y + 1e-10f);
    *(float2*)(g_unary + w * NCLS + lane * 2) = make_float2(u0, u1);
    float z0 = -u0, z1 = -u1;
    float m = fmaxf(z0, z1);
    #pragma unroll
    for (int o = 16; o; o >>= 1) m = fmaxf(m, __shfl_xor_sync(0xffffffffu, m, o));
    float e0 = expf(z0 - m), e1 = expf(z1 - m);
    float sm = e0 + e1;
    #pragma unroll
    for (int o = 16; o; o >>= 1) sm += __shfl_xor_sync(0xffffffffu, sm, o);
    float inv = 1.f / sm;
    *(float2*)(g_Ya + w * NCLS + lane * 2) = make_float2(e0 * inv, e1 * inv);
}

// ---------------- bf16 mma.sync symmetric GEMM: g_dotsb = fnb @ fnb^T ----------------
#define BM 128
#define BN 128
#define BKC 32
#define AST 40     // padded smem row stride (bf16): 80 B
#define TST 136    // transpose-staging stride (bf16): 272 B (16B aligned)
#define NBLK (NROWS / BM) // 64

__global__ void __launch_bounds__(256) gemm_mma_kernel() {
    __shared__ __align__(16) unsigned char pool[40960];
    __nv_bfloat16 (*As)[BM][AST] = (__nv_bfloat16 (*)[BM][AST])pool;
    __nv_bfloat16 (*Bs)[BN][AST] = (__nv_bfloat16 (*)[BN][AST])(pool + 20480);
    __nv_bfloat16 (*Ts)[TST] = (__nv_bfloat16 (*)[TST])pool;  // reused for mirror

    // triangular block decode
    int tt = blockIdx.x, bi = 0;
    while (tt >= NBLK - bi) { tt -= NBLK - bi; bi++; }
    int bj = bi + tt;
    int iBase = bi * BM, jBase = bj * BN;

    int tid = threadIdx.x, lane = tid & 31, wid = tid >> 5;
    int wm = wid & 1, wn = wid >> 1;   // warp tile 64x32 at (wm*64, wn*32)

    int lrow = tid >> 2;
    int lch = (tid & 3) * 8;
    const __nv_bfloat16* gA = g_fnb + (size_t)(iBase + lrow) * FDIM + lch;
    const __nv_bfloat16* gB = g_fnb + (size_t)(jBase + lrow) * FDIM + lch;

    float acc[4][4][4];
    #pragma unroll
    for (int mi = 0; mi < 4; ++mi)
        #pragma unroll
        for (int ni = 0; ni < 4; ++ni)
            #pragma unroll
            for (int q = 0; q < 4; ++q) acc[mi][ni][q] = 0.f;

    int aRow = wm * 64 + (lane & 15);
    int aCol = ((lane >> 4) << 3);
    int bRow = wn * 32 + (lane & 7);
    int bCol = ((lane >> 3) & 1) << 3;

    cp_async16(smem_u32(&As[0][lrow][lch]), gA);
    cp_async16(smem_u32(&As[0][lrow + 64][lch]), gA + 64 * FDIM);
    cp_async16(smem_u32(&Bs[0][lrow][lch]), gB);
    cp_async16(smem_u32(&Bs[0][lrow + 64][lch]), gB + 64 * FDIM);
    cp_commit();

    #pragma unroll 1
    for (int kk = 0; kk < FDIM / BKC; ++kk) {
        int buf = kk & 1;
        cp_wait0();
        __syncthreads();
        if (kk < FDIM / BKC - 1) {
            int nb = buf ^ 1, k0 = (kk + 1) * BKC;
            cp_async16(smem_u32(&As[nb][lrow][lch]), gA + k0);
            cp_async16(smem_u32(&As[nb][lrow + 64][lch]), gA + 64 * FDIM + k0);
            cp_async16(smem_u32(&Bs[nb][lrow][lch]), gB + k0);
            cp_async16(smem_u32(&Bs[nb][lrow + 64][lch]), gB + 64 * FDIM + k0);
            cp_commit();
        }
        #pragma unroll
        for (int ks = 0; ks < 2; ++ks) {
            int k0 = ks * 16;
            uint32_t a[4][4], b[4][2];
            #pragma unroll
            for (int mi = 0; mi < 4; ++mi) {
                uint32_t ad = smem_u32(&As[buf][aRow + mi * 16][k0 + aCol]);
                asm volatile(
                    "ldmatrix.sync.aligned.m8n8.x4.shared.b16 {%0,%1,%2,%3}, [%4];"
                    : "=r"(a[mi][0]), "=r"(a[mi][1]), "=r"(a[mi][2]), "=r"(a[mi][3])
                    : "r"(ad));
            }
            #pragma unroll
            for (int ni = 0; ni < 4; ++ni) {
                uint32_t bd = smem_u32(&Bs[buf][bRow + ni * 8][k0 + bCol]);
                asm volatile(
                    "ldmatrix.sync.aligned.m8n8.x2.shared.b16 {%0,%1}, [%2];"
                    : "=r"(b[ni][0]), "=r"(b[ni][1])
                    : "r"(bd));
            }
            #pragma unroll
            for (int mi = 0; mi < 4; ++mi)
                #pragma unroll
                for (int ni = 0; ni < 4; ++ni)
                    asm volatile(
                        "mma.sync.aligned.m16n8k16.row.col.f32.bf16.bf16.f32 "
                        "{%0,%1,%2,%3}, {%4,%5,%6,%7}, {%8,%9}, {%0,%1,%2,%3};"
                        : "+f"(acc[mi][ni][0]), "+f"(acc[mi][ni][1]),
                          "+f"(acc[mi][ni][2]), "+f"(acc[mi][ni][3])
                        : "r"(a[mi][0]), "r"(a[mi][1]), "r"(a[mi][2]), "r"(a[mi][3]),
                          "r"(b[ni][0]), "r"(b[ni][1]));
        }
        __syncthreads();
    }

    // main tile write (rows iBase block, cols jBase block)
    int r0 = wm * 64 + (lane >> 2);
    int c0 = wn * 32 + (lane & 3) * 2;
    #pragma unroll
    for (int mi = 0; mi < 4; ++mi)
        #pragma unroll
        for (int ni = 0; ni < 4; ++ni) {
            size_t row = (size_t)(iBase + r0 + mi * 16);
            int col = jBase + c0 + ni * 8;
            *(uint32_t*)(g_dotsb + row * NROWS + col) =
                packbf(acc[mi][ni][0], acc[mi][ni][1]);
            *(uint32_t*)(g_dotsb + (row + 8) * NROWS + col) =
                packbf(acc[mi][ni][2], acc[mi][ni][3]);
        }

    // mirror: stage transposed bf16 tile in smem, write coalesced
    if (bi != bj) {
        #pragma unroll
        for (int mi = 0; mi < 4; ++mi)
            #pragma unroll
            for (int ni = 0; ni < 4; ++ni) {
                int rr = r0 + mi * 16;
                int cc = c0 + ni * 8;
                Ts[cc][rr]         = __float2bfloat16(acc[mi][ni][0]);
                Ts[cc + 1][rr]     = __float2bfloat16(acc[mi][ni][1]);
                Ts[cc][rr + 8]     = __float2bfloat16(acc[mi][ni][2]);
                Ts[cc + 1][rr + 8] = __float2bfloat16(acc[mi][ni][3]);
            }
        __syncthreads();
        #pragma unroll
        for (int q = 0; q < 8; ++q) {
            int idx = q * 256 + tid;       // 2048 uint4 chunks: 16 chunks per 128-col row
            int c = idx >> 4;              // 0..127
            int ch = (idx & 15) * 8;       // 0..120
            uint4 v = *(const uint4*)&Ts[c][ch];
            *(uint4*)(g_dotsb + (size_t)(jBase + c) * NROWS + iBase + ch) = v;
        }
    }
}

// ---------------- fused top-16 + exact refine -> top-5 neighbors ----------------
__device__ __forceinline__ bool cless(float v1, int i1, float v2, int i2) {
    return (v1 < v2) || (v1 == v2 && i1 < i2);
}

__global__ void __launch_bounds__(128) knn_kernel() {
    int row = blockIdx.x;
    int t = threadIdx.x, lane = t & 31, wid = t >> 5;
    float sqi = g_sq[row];
    const __nv_bfloat16* __restrict__ dr = g_dotsb + (size_t)row * NROWS;
    const float* __restrict__ sq = g_sq;

    float bv[NCAND]; int bx[NCAND];
    #pragma unroll
    for (int k = 0; k < NCAND; ++k) { bv[k] = FLT_MAX; bx[k] = 0x7fffffff; }

    for (int s = 0; s < 8; ++s) {
        int j0 = (s * 128 + t) * 8;
        uint4 v = *(const uint4*)(dr + j0);
        uint32_t u[4] = {v.x, v.y, v.z, v.w};
        float4 q0 = *(const float4*)(sq + j0);
        float4 q1 = *(const float4*)(sq + j0 + 4);
        float qq[8] = {q0.x, q0.y, q0.z, q0.w, q1.x, q1.y, q1.z, q1.w};
        #pragma unroll
        for (int p = 0; p < 4; ++p) {
            __nv_bfloat162 bb = *(__nv_bfloat162*)&u[p];
            #pragma unroll
            for (int h = 0; h < 2; ++h) {
                int jj = j0 + p * 2 + h;
                float dot = h ? __bfloat162float(bb.y) : __bfloat162float(bb.x);
                float d = fmaxf(sqi + qq[p * 2 + h] - 2.f * dot, 0.f);
                if (cless(d, jj, bv[NCAND - 1], bx[NCAND - 1])) {
                    bv[NCAND - 1] = d; bx[NCAND - 1] = jj;
                    #pragma unroll
                    for (int k = NCAND - 1; k > 0; --k) {
                        bool sw = cless(bv[k], bx[k], bv[k - 1], bx[k - 1]);
                        float tv = bv[k - 1]; int ti = bx[k - 1];
                        bv[k - 1] = sw ? bv[k] : bv[k - 1];
                        bx[k - 1] = sw ? bx[k] : bx[k - 1];
                        bv[k] = sw ? tv : bv[k];
                        bx[k] = sw ? ti : bx[k];
                    }
                }
            }
        }
    }

    __shared__ float sv[2][128 * NCAND];
    __shared__ int   si[2][128 * NCAND];
    #pragma unroll
    for (int k = 0; k < NCAND; ++k) { sv[0][t * NCAND + k] = bv[k]; si[0][t * NCAND + k] = bx[k]; }

    int cur = 0;
    for (int s = 64; s >= 1; s >>= 1) {
        __syncthreads();
        if (t < s) {
            const float* Av = &sv[cur][t * NCAND];       const int* Ai = &si[cur][t * NCAND];
            const float* Bv = &sv[cur][(t + s) * NCAND]; const int* Bi = &si[cur][(t + s) * NCAND];
            float* Ov = &sv[cur ^ 1][t * NCAND];         int* Oi = &si[cur ^ 1][t * NCAND];
            int p = 0, q = 0;
            #pragma unroll
            for (int r = 0; r < NCAND; ++r) {
                float av = Av[p]; int ai = Ai[p];
                float bw = Bv[q]; int bi2 = Bi[q];
                if (cless(av, ai, bw, bi2)) { Ov[r] = av; Oi[r] = ai; ++p; }
                else                        { Ov[r] = bw; Oi[r] = bi2; ++q; }
            }
        }
        cur ^= 1;
    }
    __syncthreads();

    // refine: exact fp32 dists for the 16 candidates (4 per warp)
    __shared__ int   sc[NCAND];
    __shared__ float sdv[NCAND];
    __shared__ int   sdj[NCAND];
    if (t < NCAND) sc[t] = si[cur][t];
    __syncthreads();

    const float* fr = g_fn + (size_t)row * FDIM;
    float4 m0 = *(const float4*)(fr + lane * 8);
    float4 m1 = *(const float4*)(fr + lane * 8 + 4);
    #pragma unroll
    for (int c = 0; c < 4; ++c) {
        int ci = wid * 4 + c;
        int j = sc[ci];
        const float* fj = g_fn + (size_t)j * FDIM;
        float4 a0 = *(const float4*)(fj + lane * 8);
        float4 a1 = *(const float4*)(fj + lane * 8 + 4);
        float acc = m0.x * a0.x + m0.y * a0.y + m0.z * a0.z + m0.w * a0.w
                  + m1.x * a1.x + m1.y * a1.y + m1.z * a1.z + m1.w * a1.w;
        #pragma unroll
        for (int o = 16; o; o >>= 1) acc += __shfl_xor_sync(0xffffffffu, acc, o);
        if (lane == 0) {
            sdv[ci] = fmaxf(sqi + g_sq[j] - 2.f * acc, 0.f);
            sdj[ci] = j;
        }
    }
    __syncthreads();
    if (t == 0) {
        #pragma unroll
        for (int r = 0; r < KNNK; ++r) {
            float best = FLT_MAX; int bi2 = 0x7fffffff, bc = -1;
            for (int c = 0; c < NCAND; ++c)
                if (sdj[c] != row && cless(sdv[c], sdj[c], best, bi2)) {
                    best = sdv[c]; bi2 = sdj[c]; bc = c;
                }
            g_idx[row * KNNK + r] = bi2;
            sdv[bc] = FLT_MAX; sdj[bc] = 0x7fffffff;
        }
    }
}

// ---------------- one lean mean-field iteration (warp per row) ----------------
// No energy, no convergence machinery: buffers passed by host, last iter
// writes straight to d_out.
__global__ void __launch_bounds__(256) iter_kernel(const float* __restrict__ Yold,
                                                   float* __restrict__ Ynew) {
    int row = blockIdx.x * 8 + (threadIdx.x >> 5);
    int lane = threadIdx.x & 31;

    const int* nb = &g_idx[row * KNNK];
    int n0 = __ldg(nb), n1 = __ldg(nb + 1), n2 = __ldg(nb + 2),
        n3 = __ldg(nb + 3), n4 = __ldg(nb + 4);

    float2 u = *(const float2*)&g_unary[row * NCLS + lane * 2];
    float2 p0 = __ldcg((const float2*)(Yold + (size_t)n0 * NCLS + lane * 2));
    float2 p1 = __ldcg((const float2*)(Yold + (size_t)n1 * NCLS + lane * 2));
    float2 p2 = __ldcg((const float2*)(Yold + (size_t)n2 * NCLS + lane * 2));
    float2 p3 = __ldcg((const float2*)(Yold + (size_t)n3 * NCLS + lane * 2));
    float2 p4 = __ldcg((const float2*)(Yold + (size_t)n4 * NCLS + lane * 2));

    float z0 = -u.x + p0.x + p1.x + p2.x + p3.x + p4.x;  // LAM = 1
    float z1 = -u.y + p0.y + p1.y + p2.y + p3.y + p4.y;
    float m = fmaxf(z0, z1);
    #pragma unroll
    for (int o = 16; o; o >>= 1) m = fmaxf(m, __shfl_xor_sync(0xffffffffu, m, o));
    float e0 = __expf(z0 - m), e1 = __expf(z1 - m);
    float sm = e0 + e1;
    #pragma unroll
    for (int o = 16; o; o >>= 1) sm += __shfl_xor_sync(0xffffffffu, sm, o);
    float inv = 1.f / sm;
    *(float2*)(Ynew + (size_t)row * NCLS + lane * 2) = make_float2(e0 * inv, e1 * inv);
}

// ---------------- host entry ----------------
extern "C" void kernel_launch(void* const* d_in, const int* in_sizes, int n_in,
                              void* d_out, int out_size) {
    const float* scores = (const float*)d_in[0];
    const float* feats  = (const float*)d_in[1];
    if (n_in >= 2 && in_sizes[0] == NROWS * FDIM) {
        scores = (const float*)d_in[1];
        feats  = (const float*)d_in[0];
    }
    (void)out_size;

    normalize_kernel<<<NROWS, FDIM>>>(feats);
    unary_y0_kernel<<<NROWS / 8, 256>>>(scores);
    gemm_mma_kernel<<<NBLK * (NBLK + 1) / 2, 256>>>();
    knn_kernel<<<NROWS, 128>>>();

    // 100 iterations as dependent launches; device symbols resolved once.
    float* dYa = nullptr;
    float* dYb = nullptr;
    cudaGetSymbolAddress((void**)&dYa, g_Ya);
    cudaGetSymbolAddress((void**)&dYb, g_Yb);
    float* outp = (float*)d_out;
    for (int it = 0; it < MAXSTEPS; ++it) {
        const float* Yold = (it & 1) ? dYb : dYa;
        float* Ynew = (it == MAXSTEPS - 1) ? outp : ((it & 1) ? dYa : dYb);
        iter_kernel<<<NROWS / 8, 256>>>(Yold, Ynew);
    }
}

// round 14
// speedup vs baseline: 10.6437x; 5.2759x over previous
#include <cuda_runtime.h>
#include <cuda_bf16.h>
#include <math.h>
#include <float.h>
#include <stdint.h>

#define NROWS 8192
#define FDIM 256
#define NCLS 64
#define KNNK 5
#define MAXSTEPS 100
#define LOOPBLK 256
#define CANDMAX 256

// ---------------- device scratch ----------------
__device__ float          g_fn[NROWS * FDIM];
__device__ __nv_bfloat16  g_fnb[NROWS * FDIM];
__device__ float          g_sq[NROWS];
__device__ __nv_bfloat16  g_dotsb[(size_t)NROWS * NROWS];   // now bf16 DISTANCES
__device__ float          g_unary[NROWS * NCLS];
__device__ float          g_Ya[NROWS * NCLS];
__device__ float          g_Yb[NROWS * NCLS];
__device__ int            g_idx[NROWS * KNNK];
__device__ float          g_EpartF[2][LOOPBLK];
__device__ unsigned       g_barA;
__device__ volatile unsigned g_barE;

// ---------------- helpers ----------------
__device__ __forceinline__ uint32_t smem_u32(const void* p) {
    uint32_t a;
    asm("{ .reg .u64 t; cvta.to.shared.u64 t, %1; cvt.u32.u64 %0, t; }" : "=r"(a) : "l"(p));
    return a;
}
__device__ __forceinline__ uint32_t packbf(float lo, float hi) {
    uint32_t r;
    asm("cvt.rn.bf16x2.f32 %0, %1, %2;" : "=r"(r) : "f"(hi), "f"(lo)); // d.lo = %2
    return r;
}
__device__ __forceinline__ void cp_async16(uint32_t saddr, const void* gaddr) {
    asm volatile("cp.async.cg.shared.global [%0], [%1], 16;" :: "r"(saddr), "l"(gaddr));
}
__device__ __forceinline__ void cp_commit() { asm volatile("cp.async.commit_group;"); }
__device__ __forceinline__ void cp_wait0() { asm volatile("cp.async.wait_group 0;"); }

// ---------------- init ----------------
__global__ void init_kernel() {
    g_barA = 0;
    g_barE = 0;
}

// ---------------- normalize feats (fp32 + bf16), compute sq ----------------
__global__ void normalize_kernel(const float* __restrict__ feats) {
    int row = blockIdx.x;
    int t = threadIdx.x;
    __shared__ float red[8];
    float x = feats[row * FDIM + t];
    float v = x * x;
    #pragma unroll
    for (int o = 16; o; o >>= 1) v += __shfl_xor_sync(0xffffffffu, v, o);
    if ((t & 31) == 0) red[t >> 5] = v;
    __syncthreads();
    float tot = red[0] + red[1] + red[2] + red[3] + red[4] + red[5] + red[6] + red[7];
    float y = x / fmaxf(sqrtf(tot), 1e-12f);
    g_fn[row * FDIM + t] = y;
    g_fnb[row * FDIM + t] = __float2bfloat16(y);
    float v2 = y * y;
    #pragma unroll
    for (int o = 16; o; o >>= 1) v2 += __shfl_xor_sync(0xffffffffu, v2, o);
    __syncthreads();
    if ((t & 31) == 0) red[t >> 5] = v2;
    __syncthreads();
    if (t == 0)
        g_sq[row] = red[0] + red[1] + red[2] + red[3] + red[4] + red[5] + red[6] + red[7];
}

// ---------------- unary + Y0 ----------------
__global__ void unary_y0_kernel(const float* __restrict__ scores) {
    int w = blockIdx.x * (blockDim.x >> 5) + (threadIdx.x >> 5);
    int lane = threadIdx.x & 31;
    if (w >= NROWS) return;
    float2 s = *(const float2*)(scores + w * NCLS + lane * 2);
    float u0 = -logf(s.x + 1e-10f);
    float u1 = -logf(s.y + 1e-10f);
    *(float2*)(g_unary + w * NCLS + lane * 2) = make_float2(u0, u1);
    float z0 = -u0, z1 = -u1;
    float m = fmaxf(z0, z1);
    #pragma unroll
    for (int o = 16; o; o >>= 1) m = fmaxf(m, __shfl_xor_sync(0xffffffffu, m, o));
    float e0 = expf(z0 - m), e1 = expf(z1 - m);
    float sm = e0 + e1;
    #pragma unroll
    for (int o = 16; o; o >>= 1) sm += __shfl_xor_sync(0xffffffffu, sm, o);
    float inv = 1.f / sm;
    *(float2*)(g_Ya + w * NCLS + lane * 2) = make_float2(e0 * inv, e1 * inv);
}

// ---------------- bf16 mma.sync symmetric GEMM -> bf16 DISTANCE matrix ----------------
#define BM 128
#define BN 128
#define BKC 32
#define AST 40     // padded smem row stride (bf16): 80 B
#define TST 136    // transpose-staging stride (bf16): 272 B (16B aligned)
#define NBLK (NROWS / BM) // 64

__global__ void __launch_bounds__(256) gemm_mma_kernel() {
    __shared__ __align__(16) unsigned char pool[40960];
    __nv_bfloat16 (*As)[BM][AST] = (__nv_bfloat16 (*)[BM][AST])pool;
    __nv_bfloat16 (*Bs)[BN][AST] = (__nv_bfloat16 (*)[BN][AST])(pool + 20480);
    __nv_bfloat16 (*Ts)[TST] = (__nv_bfloat16 (*)[TST])pool;  // reused for mirror

    // triangular block decode
    int tt = blockIdx.x, bi = 0;
    while (tt >= NBLK - bi) { tt -= NBLK - bi; bi++; }
    int bj = bi + tt;
    int iBase = bi * BM, jBase = bj * BN;

    int tid = threadIdx.x, lane = tid & 31, wid = tid >> 5;
    int wm = wid & 1, wn = wid >> 1;   // warp tile 64x32 at (wm*64, wn*32)

    int lrow = tid >> 2;
    int lch = (tid & 3) * 8;
    const __nv_bfloat16* gA = g_fnb + (size_t)(iBase + lrow) * FDIM + lch;
    const __nv_bfloat16* gB = g_fnb + (size_t)(jBase + lrow) * FDIM + lch;

    float acc[4][4][4];
    #pragma unroll
    for (int mi = 0; mi < 4; ++mi)
        #pragma unroll
        for (int ni = 0; ni < 4; ++ni)
            #pragma unroll
            for (int q = 0; q < 4; ++q) acc[mi][ni][q] = 0.f;

    int aRow = wm * 64 + (lane & 15);
    int aCol = ((lane >> 4) << 3);
    int bRow = wn * 32 + (lane & 7);
    int bCol = ((lane >> 3) & 1) << 3;

    cp_async16(smem_u32(&As[0][lrow][lch]), gA);
    cp_async16(smem_u32(&As[0][lrow + 64][lch]), gA + 64 * FDIM);
    cp_async16(smem_u32(&Bs[0][lrow][lch]), gB);
    cp_async16(smem_u32(&Bs[0][lrow + 64][lch]), gB + 64 * FDIM);
    cp_commit();

    #pragma unroll 1
    for (int kk = 0; kk < FDIM / BKC; ++kk) {
        int buf = kk & 1;
        cp_wait0();
        __syncthreads();
        if (kk < FDIM / BKC - 1) {
            int nb = buf ^ 1, k0 = (kk + 1) * BKC;
            cp_async16(smem_u32(&As[nb][lrow][lch]), gA + k0);
            cp_async16(smem_u32(&As[nb][lrow + 64][lch]), gA + 64 * FDIM + k0);
            cp_async16(smem_u32(&Bs[nb][lrow][lch]), gB + k0);
            cp_async16(smem_u32(&Bs[nb][lrow + 64][lch]), gB + 64 * FDIM + k0);
            cp_commit();
        }
        #pragma unroll
        for (int ks = 0; ks < 2; ++ks) {
            int k0 = ks * 16;
            uint32_t a[4][4], b[4][2];
            #pragma unroll
            for (int mi = 0; mi < 4; ++mi) {
                uint32_t ad = smem_u32(&As[buf][aRow + mi * 16][k0 + aCol]);
                asm volatile(
                    "ldmatrix.sync.aligned.m8n8.x4.shared.b16 {%0,%1,%2,%3}, [%4];"
                    : "=r"(a[mi][0]), "=r"(a[mi][1]), "=r"(a[mi][2]), "=r"(a[mi][3])
                    : "r"(ad));
            }
            #pragma unroll
            for (int ni = 0; ni < 4; ++ni) {
                uint32_t bd = smem_u32(&Bs[buf][bRow + ni * 8][k0 + bCol]);
                asm volatile(
                    "ldmatrix.sync.aligned.m8n8.x2.shared.b16 {%0,%1}, [%2];"
                    : "=r"(b[ni][0]), "=r"(b[ni][1])
                    : "r"(bd));
            }
            #pragma unroll
            for (int mi = 0; mi < 4; ++mi)
                #pragma unroll
                for (int ni = 0; ni < 4; ++ni)
                    asm volatile(
                        "mma.sync.aligned.m16n8k16.row.col.f32.bf16.bf16.f32 "
                        "{%0,%1,%2,%3}, {%4,%5,%6,%7}, {%8,%9}, {%0,%1,%2,%3};"
                        : "+f"(acc[mi][ni][0]), "+f"(acc[mi][ni][1]),
                          "+f"(acc[mi][ni][2]), "+f"(acc[mi][ni][3])
                        : "r"(a[mi][0]), "r"(a[mi][1]), "r"(a[mi][2]), "r"(a[mi][3]),
                          "r"(b[ni][0]), "r"(b[ni][1]));
        }
        __syncthreads();
    }

    // convert accumulators to distances: d = max(sqi + sqj - 2*dot, 0)
    int r0 = wm * 64 + (lane >> 2);
    int c0 = wn * 32 + (lane & 3) * 2;
    float sqr[8], sqc[8];
    #pragma unroll
    for (int mi = 0; mi < 4; ++mi) {
        sqr[2 * mi]     = __ldg(&g_sq[iBase + r0 + mi * 16]);
        sqr[2 * mi + 1] = __ldg(&g_sq[iBase + r0 + mi * 16 + 8]);
    }
    #pragma unroll
    for (int ni = 0; ni < 4; ++ni) {
        sqc[2 * ni]     = __ldg(&g_sq[jBase + c0 + ni * 8]);
        sqc[2 * ni + 1] = __ldg(&g_sq[jBase + c0 + ni * 8 + 1]);
    }
    float dd[4][4][4];
    #pragma unroll
    for (int mi = 0; mi < 4; ++mi)
        #pragma unroll
        for (int ni = 0; ni < 4; ++ni) {
            dd[mi][ni][0] = fmaxf(fmaf(-2.f, acc[mi][ni][0], sqr[2 * mi] + sqc[2 * ni]), 0.f);
            dd[mi][ni][1] = fmaxf(fmaf(-2.f, acc[mi][ni][1], sqr[2 * mi] + sqc[2 * ni + 1]), 0.f);
            dd[mi][ni][2] = fmaxf(fmaf(-2.f, acc[mi][ni][2], sqr[2 * mi + 1] + sqc[2 * ni]), 0.f);
            dd[mi][ni][3] = fmaxf(fmaf(-2.f, acc[mi][ni][3], sqr[2 * mi + 1] + sqc[2 * ni + 1]), 0.f);
        }

    // main tile write
    #pragma unroll
    for (int mi = 0; mi < 4; ++mi)
        #pragma unroll
        for (int ni = 0; ni < 4; ++ni) {
            size_t row = (size_t)(iBase + r0 + mi * 16);
            int col = jBase + c0 + ni * 8;
            *(uint32_t*)(g_dotsb + row * NROWS + col) =
                packbf(dd[mi][ni][0], dd[mi][ni][1]);
            *(uint32_t*)(g_dotsb + (row + 8) * NROWS + col) =
                packbf(dd[mi][ni][2], dd[mi][ni][3]);
        }

    // mirror (distance matrix is symmetric): smem-staged transpose
    if (bi != bj) {
        #pragma unroll
        for (int mi = 0; mi < 4; ++mi)
            #pragma unroll
            for (int ni = 0; ni < 4; ++ni) {
                int rr = r0 + mi * 16;
                int cc = c0 + ni * 8;
                Ts[cc][rr]         = __float2bfloat16(dd[mi][ni][0]);
                Ts[cc + 1][rr]     = __float2bfloat16(dd[mi][ni][1]);
                Ts[cc][rr + 8]     = __float2bfloat16(dd[mi][ni][2]);
                Ts[cc + 1][rr + 8] = __float2bfloat16(dd[mi][ni][3]);
            }
        __syncthreads();
        #pragma unroll
        for (int q = 0; q < 8; ++q) {
            int idx = q * 256 + tid;       // 2048 uint4 chunks: 16 per 128-col row
            int c = idx >> 4;              // 0..127
            int ch = (idx & 15) * 8;       // 0..120
            uint4 v = *(const uint4*)&Ts[c][ch];
            *(uint4*)(g_dotsb + (size_t)(jBase + c) * NROWS + iBase + ch) = v;
        }
    }
}

// ---------------- knn: threshold-select candidates + exact refine ----------------
__device__ __forceinline__ bool cless(float v1, int i1, float v2, int i2) {
    return (v1 < v2) || (v1 == v2 && i1 < i2);
}

__global__ void __launch_bounds__(128) knn_kernel() {
    __shared__ uint32_t sMin[128];
    __shared__ uint32_t sTau;
    __shared__ int sCnt;
    __shared__ int sCand[CANDMAX];
    __shared__ float sDv[CANDMAX];
    __shared__ int sDj[CANDMAX];

    int row = blockIdx.x;
    int t = threadIdx.x, lane = t & 31, wid = t >> 5;
    const uint4* __restrict__ dr = (const uint4*)(g_dotsb + (size_t)row * NROWS);

    // Pass A: per-thread min over 64 bf16 distances (8 uint4, kept in regs)
    uint4 vv[8];
    __nv_bfloat162 mn;
    #pragma unroll
    for (int i = 0; i < 8; ++i) {
        uint4 v = dr[i * 128 + t];
        vv[i] = v;
        __nv_bfloat162 a = *reinterpret_cast<__nv_bfloat162*>(&v.x);
        __nv_bfloat162 b = *reinterpret_cast<__nv_bfloat162*>(&v.y);
        __nv_bfloat162 c = *reinterpret_cast<__nv_bfloat162*>(&v.z);
        __nv_bfloat162 d = *reinterpret_cast<__nv_bfloat162*>(&v.w);
        __nv_bfloat162 m = __hmin2(__hmin2(a, b), __hmin2(c, d));
        mn = (i == 0) ? m : __hmin2(mn, m);
    }
    sMin[t] = (uint32_t)__bfloat16_as_ushort(__hmin(mn.x, mn.y));
    __syncthreads();

    // warp 0: tau = 16th smallest of the 128 per-thread minima
    // (>=16 elements <= tau, so d(16) <= tau -> all true top-6 are <= tau)
    if (t < 32) {
        uint32_t v0 = (sMin[t] << 16) | t;
        uint32_t v1 = (sMin[t + 32] << 16) | (t + 32);
        uint32_t v2 = (sMin[t + 64] << 16) | (t + 64);
        uint32_t v3 = (sMin[t + 96] << 16) | (t + 96);
        uint32_t tau = 0;
        #pragma unroll
        for (int r = 0; r < 16; ++r) {
            uint32_t g = min(min(v0, v1), min(v2, v3));
            #pragma unroll
            for (int o = 16; o; o >>= 1) g = min(g, __shfl_xor_sync(0xffffffffu, g, o));
            tau = g >> 16;
            if (v0 == g) v0 = 0xFFFFFFFFu;
            if (v1 == g) v1 = 0xFFFFFFFFu;
            if (v2 == g) v2 = 0xFFFFFFFFu;
            if (v3 == g) v3 = 0xFFFFFFFFu;
        }
        if (t == 0) { sTau = tau; sCnt = 0; }
    }
    __syncthreads();
    uint32_t tau = sTau;

    // Pass B: collect indices with d <= tau (uint16 compare valid: d >= +0)
    #pragma unroll
    for (int i = 0; i < 8; ++i) {
        int j0 = (i * 128 + t) * 8;
        uint32_t w[4] = {vv[i].x, vv[i].y, vv[i].z, vv[i].w};
        #pragma unroll
        for (int k = 0; k < 4; ++k) {
            if ((w[k] & 0xFFFFu) <= tau) {
                int p = atomicAdd(&sCnt, 1);
                if (p < CANDMAX) sCand[p] = j0 + k * 2;
            }
            if ((w[k] >> 16) <= tau) {
                int p = atomicAdd(&sCnt, 1);
                if (p < CANDMAX) sCand[p] = j0 + k * 2 + 1;
            }
        }
    }
    __syncthreads();
    int C = min(sCnt, CANDMAX);

    // exact fp32 refine for all candidates (warp per candidate, round robin)
    float sqi = g_sq[row];
    const float* fr = g_fn + (size_t)row * FDIM;
    float4 m0 = *(const float4*)(fr + lane * 8);
    float4 m1 = *(const float4*)(fr + lane * 8 + 4);
    for (int c = wid; c < C; c += 4) {
        int j = sCand[c];
        const float* fj = g_fn + (size_t)j * FDIM;
        float4 a0 = *(const float4*)(fj + lane * 8);
        float4 a1 = *(const float4*)(fj + lane * 8 + 4);
        float acc = m0.x * a0.x + m0.y * a0.y + m0.z * a0.z + m0.w * a0.w
                  + m1.x * a1.x + m1.y * a1.y + m1.z * a1.z + m1.w * a1.w;
        #pragma unroll
        for (int o = 16; o; o >>= 1) acc += __shfl_xor_sync(0xffffffffu, acc, o);
        if (lane == 0) {
            sDv[c] = fmaxf(sqi + g_sq[j] - 2.f * acc, 0.f);
            sDj[c] = j;
        }
    }
    __syncthreads();

    // exact top-5 (value then index tie-break), excluding self
    if (t == 0) {
        for (int r = 0; r < KNNK; ++r) {
            float best = FLT_MAX; int bi2 = 0x7fffffff, bc = -1;
            for (int c = 0; c < C; ++c)
                if (sDj[c] != row && cless(sDv[c], sDj[c], best, bi2)) {
                    best = sDv[c]; bi2 = sDj[c]; bc = c;
                }
            g_idx[row * KNNK + r] = bi2;
            sDv[bc] = FLT_MAX; sDj[bc] = 0x7fffffff;
        }
    }
}

// ---------------- persistent fused mean-field loop (R9 verbatim: measured) ----------------
__device__ __forceinline__ void grid_sync_(unsigned epoch) {
    __syncthreads();
    if (threadIdx.x == 0) {
        __threadfence();
        unsigned prev = atomicAdd(&g_barA, 1u);
        if (prev == epoch * LOOPBLK - 1) {
            __threadfence();
            g_barE = epoch;
        } else {
            while (g_barE < epoch) { __nanosleep(32); }
            __threadfence();
        }
    }
    __syncthreads();
}

#define RPB (NROWS / LOOPBLK)   // 32 rows per block

__global__ void __launch_bounds__(256) loop_kernel(float* __restrict__ out) {
    __shared__ float sU[RPB * NCLS];
    __shared__ int sNb[RPB * KNNK];
    __shared__ float sWE[8];
    __shared__ float sEsh;
    __shared__ int sCv;
    int b = blockIdx.x, tid = threadIdx.x, wip = tid >> 5, lane = tid & 31;
    int row0 = b * RPB;

    for (int i = tid; i < RPB * NCLS / 4; i += 256)
        ((float4*)sU)[i] = ((const float4*)(g_unary + (size_t)row0 * NCLS))[i];
    for (int i = tid; i < RPB * KNNK; i += 256)
        sNb[i] = g_idx[row0 * KNNK + i];
    __syncthreads();

    float Eprev = __int_as_float(0x7F800000); // +inf
    int finalIt = MAXSTEPS - 1;

    for (int it = 0; it < MAXSTEPS; ++it) {
        const float* Yold = (it & 1) ? g_Yb : g_Ya;
        float* Ynew = (it & 1) ? g_Ya : g_Yb;
        float eAcc = 0.f;
        #pragma unroll
        for (int q = 0; q < RPB / 8; ++q) {
            int rl = wip * (RPB / 8) + q, row = row0 + rl;
            const int* nb = &sNb[rl * KNNK];
            float2 u = *(const float2*)&sU[rl * NCLS + lane * 2];
            float2 p0 = __ldcg((const float2*)(Yold + (size_t)nb[0] * NCLS + lane * 2));
            float2 p1 = __ldcg((const float2*)(Yold + (size_t)nb[1] * NCLS + lane * 2));
            float2 p2 = __ldcg((const float2*)(Yold + (size_t)nb[2] * NCLS + lane * 2));
            float2 p3 = __ldcg((const float2*)(Yold + (size_t)nb[3] * NCLS + lane * 2));
            float2 p4 = __ldcg((const float2*)(Yold + (size_t)nb[4] * NCLS + lane * 2));
            float z0 = -u.x + p0.x + p1.x + p2.x + p3.x + p4.x;
            float z1 = -u.y + p0.y + p1.y + p2.y + p3.y + p4.y;
            float m = fmaxf(z0, z1);
            #pragma unroll
            for (int o = 16; o; o >>= 1) m = fmaxf(m, __shfl_xor_sync(0xffffffffu, m, o));
            float e0 = __expf(z0 - m), e1 = __expf(z1 - m);
            float sm = e0 + e1;
            #pragma unroll
            for (int o = 16; o; o >>= 1) sm += __shfl_xor_sync(0xffffffffu, sm, o);
            float inv = 1.f / sm;
            *(float2*)(Ynew + (size_t)row * NCLS + lane * 2) = make_float2(e0 * inv, e1 * inv);
            eAcc += -(m + __logf(sm)); // E_row = -logsumexp(z); fp32 like reference
        }
        if (lane == 0) sWE[wip] = eAcc;
        __syncthreads();
        if (tid == 0) {
            float p = ((((((sWE[0] + sWE[1]) + sWE[2]) + sWE[3]) + sWE[4]) + sWE[5]) + sWE[6]) + sWE[7];
            g_EpartF[it & 1][b] = p;
        }
        grid_sync_((unsigned)(it + 1));
        if (wip == 0) {
            const float4* ep4 = (const float4*)&g_EpartF[it & 1][lane * 8];
            float4 a = __ldcg(ep4);
            float4 c = __ldcg(ep4 + 1);
            float v = ((((((a.x + a.y) + a.z) + a.w) + c.x) + c.y) + c.z) + c.w;
            #pragma unroll
            for (int o = 16; o; o >>= 1) v += __shfl_xor_sync(0xffffffffu, v, o);
            if (lane == 0) {
                sEsh = v;
                sCv = (it >= 2 && fabsf(v - Eprev) <= 1e-8f * fabsf(Eprev)) ? 1 : 0;
            }
        }
        __syncthreads();
        float E = sEsh; int cv = sCv;
        Eprev = E;
        if (cv) { finalIt = it; break; }
    }

    const float* src = (finalIt & 1) ? g_Ya : g_Yb;
    for (int i = tid; i < RPB * NCLS / 4; i += 256) {
        float4 v = __ldcg(((const float4*)(src + (size_t)row0 * NCLS)) + i);
        ((float4*)(out + (size_t)row0 * NCLS))[i] = v;
    }
}

// ---------------- host entry ----------------
extern "C" void kernel_launch(void* const* d_in, const int* in_sizes, int n_in,
                              void* d_out, int out_size) {
    const float* scores = (const float*)d_in[0];
    const float* feats  = (const float*)d_in[1];
    if (n_in >= 2 && in_sizes[0] == NROWS * FDIM) {
        scores = (const float*)d_in[1];
        feats  = (const float*)d_in[0];
    }
    (void)out_size;

    init_kernel<<<1, 1>>>();
    normalize_kernel<<<NROWS, FDIM>>>(feats);
    unary_y0_kernel<<<NROWS / 8, 256>>>(scores);
    gemm_mma_kernel<<<NBLK * (NBLK + 1) / 2, 256>>>();
    knn_kernel<<<NROWS, 128>>>();
    loop_kernel<<<LOOPBLK, 256>>>((float*)d_out);
}

// round 15
// speedup vs baseline: 11.2775x; 1.0595x over previous
#include <cuda_runtime.h>
#include <cuda_bf16.h>
#include <math.h>
#include <float.h>
#include <stdint.h>

#define NROWS 8192
#define FDIM 256
#define NCLS 64
#define KNNK 5
#define MAXSTEPS 100
#define LOOPBLK 256
#define CANDMAX 256

// ---------------- device scratch ----------------
__device__ float          g_fn[NROWS * FDIM];
__device__ __nv_bfloat16  g_fnb[NROWS * FDIM];
__device__ float          g_sq[NROWS];
__device__ __nv_bfloat16  g_dotsb[(size_t)NROWS * NROWS];   // bf16 DISTANCES
__device__ float          g_unary[NROWS * NCLS];
__device__ float          g_Ya[NROWS * NCLS];
__device__ float          g_Yb[NROWS * NCLS];
__device__ int            g_idx[NROWS * KNNK];
__device__ float          g_EpartF[2][LOOPBLK];
__device__ unsigned       g_barA;
__device__ volatile unsigned g_barE;

// ---------------- helpers ----------------
__device__ __forceinline__ uint32_t smem_u32(const void* p) {
    uint32_t a;
    asm("{ .reg .u64 t; cvta.to.shared.u64 t, %1; cvt.u32.u64 %0, t; }" : "=r"(a) : "l"(p));
    return a;
}
__device__ __forceinline__ uint32_t packbf(float lo, float hi) {
    uint32_t r;
    asm("cvt.rn.bf16x2.f32 %0, %1, %2;" : "=r"(r) : "f"(hi), "f"(lo)); // d.lo = %2
    return r;
}
__device__ __forceinline__ void cp_async16(uint32_t saddr, const void* gaddr) {
    asm volatile("cp.async.cg.shared.global [%0], [%1], 16;" :: "r"(saddr), "l"(gaddr));
}
__device__ __forceinline__ void cp_commit() { asm volatile("cp.async.commit_group;"); }
__device__ __forceinline__ void cp_wait0() { asm volatile("cp.async.wait_group 0;"); }

// ---------------- normalize feats (fp32 + bf16), compute sq ----------------
__global__ void normalize_kernel(const float* __restrict__ feats) {
    int row = blockIdx.x;
    int t = threadIdx.x;
    __shared__ float red[8];
    float x = feats[row * FDIM + t];
    float v = x * x;
    #pragma unroll
    for (int o = 16; o; o >>= 1) v += __shfl_xor_sync(0xffffffffu, v, o);
    if ((t & 31) == 0) red[t >> 5] = v;
    __syncthreads();
    float tot = red[0] + red[1] + red[2] + red[3] + red[4] + red[5] + red[6] + red[7];
    float y = x / fmaxf(sqrtf(tot), 1e-12f);
    g_fn[row * FDIM + t] = y;
    g_fnb[row * FDIM + t] = __float2bfloat16(y);
    float v2 = y * y;
    #pragma unroll
    for (int o = 16; o; o >>= 1) v2 += __shfl_xor_sync(0xffffffffu, v2, o);
    __syncthreads();
    if ((t & 31) == 0) red[t >> 5] = v2;
    __syncthreads();
    if (t == 0)
        g_sq[row] = red[0] + red[1] + red[2] + red[3] + red[4] + red[5] + red[6] + red[7];
}

// ---------------- unary + Y0 (also resets loop barrier state) ----------------
__global__ void unary_y0_kernel(const float* __restrict__ scores) {
    if (blockIdx.x == 0 && threadIdx.x == 0) { g_barA = 0; g_barE = 0; }
    int w = blockIdx.x * (blockDim.x >> 5) + (threadIdx.x >> 5);
    int lane = threadIdx.x & 31;
    if (w >= NROWS) return;
    float2 s = *(const float2*)(scores + w * NCLS + lane * 2);
    float u0 = -logf(s.x + 1e-10f);
    float u1 = -logf(s.y + 1e-10f);
    *(float2*)(g_unary + w * NCLS + lane * 2) = make_float2(u0, u1);
    float z0 = -u0, z1 = -u1;
    float m = fmaxf(z0, z1);
    #pragma unroll
    for (int o = 16; o; o >>= 1) m = fmaxf(m, __shfl_xor_sync(0xffffffffu, m, o));
    float e0 = expf(z0 - m), e1 = expf(z1 - m);
    float sm = e0 + e1;
    #pragma unroll
    for (int o = 16; o; o >>= 1) sm += __shfl_xor_sync(0xffffffffu, sm, o);
    float inv = 1.f / sm;
    *(float2*)(g_Ya + w * NCLS + lane * 2) = make_float2(e0 * inv, e1 * inv);
}

// ---------------- bf16 mma.sync symmetric GEMM -> bf16 DISTANCE matrix ----------------
#define BM 128
#define BN 128
#define BKC 64
#define AST 72     // padded smem row stride (bf16): 144 B = 9 x 16B chunks (odd shift)
#define TST 136    // transpose-staging stride (bf16): 272 B
#define NBLK (NROWS / BM) // 64

__global__ void __launch_bounds__(256) gemm_mma_kernel() {
    __shared__ __align__(16) unsigned char pool[73728];
    __nv_bfloat16 (*As)[BM][AST] = (__nv_bfloat16 (*)[BM][AST])pool;
    __nv_bfloat16 (*Bs)[BN][AST] = (__nv_bfloat16 (*)[BN][AST])(pool + 36864);
    __nv_bfloat16 (*Ts)[TST] = (__nv_bfloat16 (*)[TST])pool;  // reused for mirror

    // triangular block decode
    int tt = blockIdx.x, bi = 0;
    while (tt >= NBLK - bi) { tt -= NBLK - bi; bi++; }
    int bj = bi + tt;
    int iBase = bi * BM, jBase = bj * BN;

    int tid = threadIdx.x, lane = tid & 31, wid = tid >> 5;
    int wm = wid & 1, wn = wid >> 1;   // warp tile 64x32 at (wm*64, wn*32)

    // loaders: 64 cols = 8 x 16B chunks per row; 32 rows per pass, 4 passes
    int lrow = tid >> 3;               // 0..31
    int lch = (tid & 7) * 8;           // bf16 offset of 16B chunk
    const __nv_bfloat16* gA = g_fnb + (size_t)(iBase + lrow) * FDIM + lch;
    const __nv_bfloat16* gB = g_fnb + (size_t)(jBase + lrow) * FDIM + lch;

    float acc[4][4][4];
    #pragma unroll
    for (int mi = 0; mi < 4; ++mi)
        #pragma unroll
        for (int ni = 0; ni < 4; ++ni)
            #pragma unroll
            for (int q = 0; q < 4; ++q) acc[mi][ni][q] = 0.f;

    int aRow = wm * 64 + (lane & 15);
    int aCol = ((lane >> 4) << 3);
    int bRow = wn * 32 + (lane & 7);
    int bCol = ((lane >> 3) & 1) << 3;

    // prefetch stage 0 (cols 0..63)
    #pragma unroll
    for (int p = 0; p < 4; ++p) {
        cp_async16(smem_u32(&As[0][lrow + p * 32][lch]), gA + p * 32 * FDIM);
        cp_async16(smem_u32(&Bs[0][lrow + p * 32][lch]), gB + p * 32 * FDIM);
    }
    cp_commit();

    #pragma unroll 1
    for (int kk = 0; kk < FDIM / BKC; ++kk) {
        int buf = kk & 1;
        cp_wait0();
        __syncthreads();                      // single barrier per stage
        if (kk < FDIM / BKC - 1) {
            int nb = buf ^ 1, k0 = (kk + 1) * BKC;
            #pragma unroll
            for (int p = 0; p < 4; ++p) {
                cp_async16(smem_u32(&As[nb][lrow + p * 32][lch]), gA + p * 32 * FDIM + k0);
                cp_async16(smem_u32(&Bs[nb][lrow + p * 32][lch]), gB + p * 32 * FDIM + k0);
            }
            cp_commit();
        }
        #pragma unroll
        for (int ks = 0; ks < 4; ++ks) {      // 4 x k16 per stage
            int k0 = ks * 16;
            uint32_t a[4][4], b[4][2];
            #pragma unroll
            for (int mi = 0; mi < 4; ++mi) {
                uint32_t ad = smem_u32(&As[buf][aRow + mi * 16][k0 + aCol]);
                asm volatile(
                    "ldmatrix.sync.aligned.m8n8.x4.shared.b16 {%0,%1,%2,%3}, [%4];"
                    : "=r"(a[mi][0]), "=r"(a[mi][1]), "=r"(a[mi][2]), "=r"(a[mi][3])
                    : "r"(ad));
            }
            #pragma unroll
            for (int ni = 0; ni < 4; ++ni) {
                uint32_t bd = smem_u32(&Bs[buf][bRow + ni * 8][k0 + bCol]);
                asm volatile(
                    "ldmatrix.sync.aligned.m8n8.x2.shared.b16 {%0,%1}, [%2];"
                    : "=r"(b[ni][0]), "=r"(b[ni][1])
                    : "r"(bd));
            }
            #pragma unroll
            for (int mi = 0; mi < 4; ++mi)
                #pragma unroll
                for (int ni = 0; ni < 4; ++ni)
                    asm volatile(
                        "mma.sync.aligned.m16n8k16.row.col.f32.bf16.bf16.f32 "
                        "{%0,%1,%2,%3}, {%4,%5,%6,%7}, {%8,%9}, {%0,%1,%2,%3};"
                        : "+f"(acc[mi][ni][0]), "+f"(acc[mi][ni][1]),
                          "+f"(acc[mi][ni][2]), "+f"(acc[mi][ni][3])
                        : "r"(a[mi][0]), "r"(a[mi][1]), "r"(a[mi][2]), "r"(a[mi][3]),
                          "r"(b[ni][0]), "r"(b[ni][1]));
        }
        // no tail sync: next stage's wait+sync protects buffer reuse
    }

    // convert accumulators to distances: d = max(sqi + sqj - 2*dot, 0)
    int r0 = wm * 64 + (lane >> 2);
    int c0 = wn * 32 + (lane & 3) * 2;
    float sqr[8], sqc[8];
    #pragma unroll
    for (int mi = 0; mi < 4; ++mi) {
        sqr[2 * mi]     = __ldg(&g_sq[iBase + r0 + mi * 16]);
        sqr[2 * mi + 1] = __ldg(&g_sq[iBase + r0 + mi * 16 + 8]);
    }
    #pragma unroll
    for (int ni = 0; ni < 4; ++ni) {
        sqc[2 * ni]     = __ldg(&g_sq[jBase + c0 + ni * 8]);
        sqc[2 * ni + 1] = __ldg(&g_sq[jBase + c0 + ni * 8 + 1]);
    }
    float dd[4][4][4];
    #pragma unroll
    for (int mi = 0; mi < 4; ++mi)
        #pragma unroll
        for (int ni = 0; ni < 4; ++ni) {
            dd[mi][ni][0] = fmaxf(fmaf(-2.f, acc[mi][ni][0], sqr[2 * mi] + sqc[2 * ni]), 0.f);
            dd[mi][ni][1] = fmaxf(fmaf(-2.f, acc[mi][ni][1], sqr[2 * mi] + sqc[2 * ni + 1]), 0.f);
            dd[mi][ni][2] = fmaxf(fmaf(-2.f, acc[mi][ni][2], sqr[2 * mi + 1] + sqc[2 * ni]), 0.f);
            dd[mi][ni][3] = fmaxf(fmaf(-2.f, acc[mi][ni][3], sqr[2 * mi + 1] + sqc[2 * ni + 1]), 0.f);
        }

    // main tile write
    #pragma unroll
    for (int mi = 0; mi < 4; ++mi)
        #pragma unroll
        for (int ni = 0; ni < 4; ++ni) {
            size_t row = (size_t)(iBase + r0 + mi * 16);
            int col = jBase + c0 + ni * 8;
            *(uint32_t*)(g_dotsb + row * NROWS + col) =
                packbf(dd[mi][ni][0], dd[mi][ni][1]);
            *(uint32_t*)(g_dotsb + (row + 8) * NROWS + col) =
                packbf(dd[mi][ni][2], dd[mi][ni][3]);
        }

    // mirror (distance matrix is symmetric): smem-staged transpose
    if (bi != bj) {
        __syncthreads();   // all warps done reading As/Bs before pool reuse
        #pragma unroll
        for (int mi = 0; mi < 4; ++mi)
            #pragma unroll
            for (int ni = 0; ni < 4; ++ni) {
                int rr = r0 + mi * 16;
                int cc = c0 + ni * 8;
                Ts[cc][rr]         = __float2bfloat16(dd[mi][ni][0]);
                Ts[cc + 1][rr]     = __float2bfloat16(dd[mi][ni][1]);
                Ts[cc][rr + 8]     = __float2bfloat16(dd[mi][ni][2]);
                Ts[cc + 1][rr + 8] = __float2bfloat16(dd[mi][ni][3]);
            }
        __syncthreads();
        #pragma unroll
        for (int q = 0; q < 8; ++q) {
            int idx = q * 256 + tid;       // 2048 uint4 chunks: 16 per 128-col row
            int c = idx >> 4;              // 0..127
            int ch = (idx & 15) * 8;       // 0..120
            uint4 v = *(const uint4*)&Ts[c][ch];
            *(uint4*)(g_dotsb + (size_t)(jBase + c) * NROWS + iBase + ch) = v;
        }
    }
}

// ---------------- knn: threshold-select candidates + exact refine ----------------
__device__ __forceinline__ bool cless(float v1, int i1, float v2, int i2) {
    return (v1 < v2) || (v1 == v2 && i1 < i2);
}

__global__ void __launch_bounds__(128) knn_kernel() {
    __shared__ uint32_t sMin[128];
    __shared__ uint32_t sTau;
    __shared__ int sCnt;
    __shared__ int sCand[CANDMAX];
    __shared__ float sDv[CANDMAX];
    __shared__ int sDj[CANDMAX];

    int row = blockIdx.x;
    int t = threadIdx.x, lane = t & 31, wid = t >> 5;
    const uint4* __restrict__ dr = (const uint4*)(g_dotsb + (size_t)row * NROWS);

    // Pass A: per-thread min over 64 bf16 distances (8 uint4, kept in regs)
    uint4 vv[8];
    __nv_bfloat162 mn;
    #pragma unroll
    for (int i = 0; i < 8; ++i) {
        uint4 v = dr[i * 128 + t];
        vv[i] = v;
        __nv_bfloat162 a = *reinterpret_cast<__nv_bfloat162*>(&v.x);
        __nv_bfloat162 b = *reinterpret_cast<__nv_bfloat162*>(&v.y);
        __nv_bfloat162 c = *reinterpret_cast<__nv_bfloat162*>(&v.z);
        __nv_bfloat162 d = *reinterpret_cast<__nv_bfloat162*>(&v.w);
        __nv_bfloat162 m = __hmin2(__hmin2(a, b), __hmin2(c, d));
        mn = (i == 0) ? m : __hmin2(mn, m);
    }
    sMin[t] = (uint32_t)__bfloat16_as_ushort(__hmin(mn.x, mn.y));
    __syncthreads();

    // warp 0: tau = 16th smallest of the 128 per-thread minima
    if (t < 32) {
        uint32_t v0 = (sMin[t] << 16) | t;
        uint32_t v1 = (sMin[t + 32] << 16) | (t + 32);
        uint32_t v2 = (sMin[t + 64] << 16) | (t + 64);
        uint32_t v3 = (sMin[t + 96] << 16) | (t + 96);
        uint32_t tau = 0;
        #pragma unroll
        for (int r = 0; r < 16; ++r) {
            uint32_t g = min(min(v0, v1), min(v2, v3));
            #pragma unroll
            for (int o = 16; o; o >>= 1) g = min(g, __shfl_xor_sync(0xffffffffu, g, o));
            tau = g >> 16;
            if (v0 == g) v0 = 0xFFFFFFFFu;
            if (v1 == g) v1 = 0xFFFFFFFFu;
            if (v2 == g) v2 = 0xFFFFFFFFu;
            if (v3 == g) v3 = 0xFFFFFFFFu;
        }
        if (t == 0) { sTau = tau; sCnt = 0; }
    }
    __syncthreads();
    uint32_t tau = sTau;

    // Pass B: collect indices with d <= tau (uint16 compare valid: d >= +0)
    #pragma unroll
    for (int i = 0; i < 8; ++i) {
        int j0 = (i * 128 + t) * 8;
        uint32_t w[4] = {vv[i].x, vv[i].y, vv[i].z, vv[i].w};
        #pragma unroll
        for (int k = 0; k < 4; ++k) {
            if ((w[k] & 0xFFFFu) <= tau) {
                int p = atomicAdd(&sCnt, 1);
                if (p < CANDMAX) sCand[p] = j0 + k * 2;
            }
            if ((w[k] >> 16) <= tau) {
                int p = atomicAdd(&sCnt, 1);
                if (p < CANDMAX) sCand[p] = j0 + k * 2 + 1;
            }
        }
    }
    __syncthreads();
    int C = min(sCnt, CANDMAX);

    // exact fp32 refine for all candidates (warp per candidate, round robin)
    float sqi = g_sq[row];
    const float* fr = g_fn + (size_t)row * FDIM;
    float4 m0 = *(const float4*)(fr + lane * 8);
    float4 m1 = *(const float4*)(fr + lane * 8 + 4);
    for (int c = wid; c < C; c += 4) {
        int j = sCand[c];
        const float* fj = g_fn + (size_t)j * FDIM;
        float4 a0 = *(const float4*)(fj + lane * 8);
        float4 a1 = *(const float4*)(fj + lane * 8 + 4);
        float acc = m0.x * a0.x + m0.y * a0.y + m0.z * a0.z + m0.w * a0.w
                  + m1.x * a1.x + m1.y * a1.y + m1.z * a1.z + m1.w * a1.w;
        #pragma unroll
        for (int o = 16; o; o >>= 1) acc += __shfl_xor_sync(0xffffffffu, acc, o);
        if (lane == 0) {
            sDv[c] = fmaxf(sqi + g_sq[j] - 2.f * acc, 0.f);
            sDj[c] = j;
        }
    }
    __syncthreads();

    // exact top-5 (value then index tie-break), excluding self
    if (t == 0) {
        for (int r = 0; r < KNNK; ++r) {
            float best = FLT_MAX; int bi2 = 0x7fffffff, bc = -1;
            for (int c = 0; c < C; ++c)
                if (sDj[c] != row && cless(sDv[c], sDj[c], best, bi2)) {
                    best = sDv[c]; bi2 = sDj[c]; bc = c;
                }
            g_idx[row * KNNK + r] = bi2;
            sDv[bc] = FLT_MAX; sDj[bc] = 0x7fffffff;
        }
    }
}

// ---------------- persistent fused mean-field loop (measured-good R9 shape) ----------------
__device__ __forceinline__ void grid_sync_(unsigned epoch) {
    __syncthreads();
    if (threadIdx.x == 0) {
        __threadfence();
        unsigned prev = atomicAdd(&g_barA, 1u);
        if (prev == epoch * LOOPBLK - 1) {
            __threadfence();
            g_barE = epoch;
        } else {
            while (g_barE < epoch) { __nanosleep(32); }
            __threadfence();
        }
    }
    __syncthreads();
}

#define RPB (NROWS / LOOPBLK)   // 32 rows per block

__global__ void __launch_bounds__(256) loop_kernel(float* __restrict__ out) {
    __shared__ float sU[RPB * NCLS];
    __shared__ int sNb[RPB * KNNK];
    __shared__ float sWE[8];
    __shared__ float sEsh;
    __shared__ int sCv;
    int b = blockIdx.x, tid = threadIdx.x, wip = tid >> 5, lane = tid & 31;
    int row0 = b * RPB;

    for (int i = tid; i < RPB * NCLS / 4; i += 256)
        ((float4*)sU)[i] = ((const float4*)(g_unary + (size_t)row0 * NCLS))[i];
    for (int i = tid; i < RPB * KNNK; i += 256)
        sNb[i] = g_idx[row0 * KNNK + i];
    __syncthreads();

    float Eprev = __int_as_float(0x7F800000); // +inf
    int finalIt = MAXSTEPS - 1;

    for (int it = 0; it < MAXSTEPS; ++it) {
        const float* Yold = (it & 1) ? g_Yb : g_Ya;
        float* Ynew = (it & 1) ? g_Ya : g_Yb;
        float eAcc = 0.f;
        #pragma unroll
        for (int q = 0; q < RPB / 8; ++q) {
            int rl = wip * (RPB / 8) + q, row = row0 + rl;
            const int* nb = &sNb[rl * KNNK];
            float2 u = *(const float2*)&sU[rl * NCLS + lane * 2];
            float2 p0 = __ldcg((const float2*)(Yold + (size_t)nb[0] * NCLS + lane * 2));
            float2 p1 = __ldcg((const float2*)(Yold + (size_t)nb[1] * NCLS + lane * 2));
            float2 p2 = __ldcg((const float2*)(Yold + (size_t)nb[2] * NCLS + lane * 2));
            float2 p3 = __ldcg((const float2*)(Yold + (size_t)nb[3] * NCLS + lane * 2));
            float2 p4 = __ldcg((const float2*)(Yold + (size_t)nb[4] * NCLS + lane * 2));
            float z0 = -u.x + p0.x + p1.x + p2.x + p3.x + p4.x;
            float z1 = -u.y + p0.y + p1.y + p2.y + p3.y + p4.y;
            float m = fmaxf(z0, z1);
            #pragma unroll
            for (int o = 16; o; o >>= 1) m = fmaxf(m, __shfl_xor_sync(0xffffffffu, m, o));
            float e0 = __expf(z0 - m), e1 = __expf(z1 - m);
            float sm = e0 + e1;
            #pragma unroll
            for (int o = 16; o; o >>= 1) sm += __shfl_xor_sync(0xffffffffu, sm, o);
            float inv = 1.f / sm;
            *(float2*)(Ynew + (size_t)row * NCLS + lane * 2) = make_float2(e0 * inv, e1 * inv);
            eAcc += -(m + __logf(sm)); // E_row = -logsumexp(z); fp32 like reference
        }
        if (lane == 0) sWE[wip] = eAcc;
        __syncthreads();
        if (tid == 0) {
            float p = ((((((sWE[0] + sWE[1]) + sWE[2]) + sWE[3]) + sWE[4]) + sWE[5]) + sWE[6]) + sWE[7];
            g_EpartF[it & 1][b] = p;
        }
        grid_sync_((unsigned)(it + 1));
        if (wip == 0) {
            const float4* ep4 = (const float4*)&g_EpartF[it & 1][lane * 8];
            float4 a = __ldcg(ep4);
            float4 c = __ldcg(ep4 + 1);
            float v = ((((((a.x + a.y) + a.z) + a.w) + c.x) + c.y) + c.z) + c.w;
            #pragma unroll
            for (int o = 16; o; o >>= 1) v += __shfl_xor_sync(0xffffffffu, v, o);
            if (lane == 0) {
                sEsh = v;
                sCv = (it >= 2 && fabsf(v - Eprev) <= 1e-8f * fabsf(Eprev)) ? 1 : 0;
            }
        }
        __syncthreads();
        float E = sEsh; int cv = sCv;
        Eprev = E;
        if (cv) { finalIt = it; break; }
    }

    const float* src = (finalIt & 1) ? g_Ya : g_Yb;
    for (int i = tid; i < RPB * NCLS / 4; i += 256) {
        float4 v = __ldcg(((const float4*)(src + (size_t)row0 * NCLS)) + i);
        ((float4*)(out + (size_t)row0 * NCLS))[i] = v;
    }
}

// ---------------- host entry ----------------
extern "C" void kernel_launch(void* const* d_in, const int* in_sizes, int n_in,
                              void* d_out, int out_size) {
    const float* scores = (const float*)d_in[0];
    const float* feats  = (const float*)d_in[1];
    if (n_in >= 2 && in_sizes[0] == NROWS * FDIM) {
        scores = (const float*)d_in[1];
        feats  = (const float*)d_in[0];
    }
    (void)out_size;

    normalize_kernel<<<NROWS, FDIM>>>(feats);
    unary_y0_kernel<<<NROWS / 8, 256>>>(scores);
    gemm_mma_kernel<<<NBLK * (NBLK + 1) / 2, 256>>>();
    knn_kernel<<<NROWS, 128>>>();
    loop_kernel<<<LOOPBLK, 256>>>((float*)d_out);
}